// round 7
// baseline (speedup 1.0000x reference)
#include <cuda_runtime.h>
#include <cstdint>

// Problem constants
#define NN 50000
#define EE 800000

// ---------------- device scratch (no allocations allowed) ----------------
__device__ __align__(16) float g_y[NN * 64];     // pre-aggregation GEMM output
__device__ __align__(16) float g_agg[NN * 64];   // aggregation accumulator
__device__ __align__(16) float g_h[NN * 64];     // post-MLP (pre-BN) features
__device__ float g_stats[128];                   // [0:64) sum, [64:128) sumsq

// ---------------- tf32 helpers ----------------
__device__ __forceinline__ float f2tf32(float x) {
    uint32_t u;
    asm("cvt.rna.tf32.f32 %0, %1;" : "=r"(u) : "f"(x));
    return __uint_as_float(u);
}

// split x into tf32 hi + tf32 lo (3xTF32 decomposition)
__device__ __forceinline__ void tf32split(float x, float& hi, float& lo) {
    hi = f2tf32(x);
    lo = f2tf32(x - hi);
}

__device__ __forceinline__ void mma_tf32(float4& c, uint32_t a0, uint32_t a1,
                                         uint32_t a2, uint32_t a3,
                                         uint32_t b0, uint32_t b1) {
    asm volatile(
        "mma.sync.aligned.m16n8k8.row.col.f32.tf32.tf32.f32 "
        "{%0,%1,%2,%3}, {%4,%5,%6,%7}, {%8,%9}, {%0,%1,%2,%3};"
        : "+f"(c.x), "+f"(c.y), "+f"(c.z), "+f"(c.w)
        : "r"(a0), "r"(a1), "r"(a2), "r"(a3), "r"(b0), "r"(b1));
}

// ---------------------------------------------------------------------------
// Kernel A (3xTF32 tensor-core): y = act(src) @ W  (N x K @ K x 64).
// act = identity (layer 1) or BN+ReLU (layers 2,3; scale/shift from g_stats).
// Writes g_y and g_agg = (1+eps)*y. 64x64 block tile; K-chunks of 32; 8
// warps; each warp does a 16x32 tile via m16n8k8 tf32 MMA with hi/lo
// error compensation (Ah*Bh + Ah*Bl + Al*Bh).
// ---------------------------------------------------------------------------
template <int K, bool BN>
__global__ void __launch_bounds__(256) gemmA(const float* __restrict__ A,
                                             const float* __restrict__ W,
                                             const float* __restrict__ epsp,
                                             const float* __restrict__ gamma,
                                             const float* __restrict__ beta) {
    __shared__ float Ah[64][36], Al[64][36];   // 144B row stride
    __shared__ float Wh[32][72], Wl[32][72];   // 288B row stride
    __shared__ float sc[64], sh[64];

    const int tid = threadIdx.x;
    const int row0 = blockIdx.x * 64;

    const float* __restrict__ src = BN ? (const float*)g_h : A;

    if (BN) {
        if (tid < 64) {
            const float inv = 1.f / (float)NN;
            float mean = g_stats[tid] * inv;
            float var = g_stats[64 + tid] * inv - mean * mean;
            float s = gamma[tid] * rsqrtf(var + 1e-5f);
            sc[tid] = s;
            sh[tid] = beta[tid] - mean * s;
        }
        __syncthreads();
    }

    const int w = tid >> 5;
    const int lane = tid & 31;
    const int gID = lane >> 2;
    const int tig = lane & 3;
    const int mr = (w & 3) * 16;        // warp m-offset in tile
    const int nc = (w >> 2) * 32;       // warp n-offset in tile

    float4 c[4] = {};

    for (int kc = 0; kc < K; kc += 32) {
        // stage A chunk (64 rows x 32 k), BN+ReLU applied, hi/lo split
#pragma unroll
        for (int l = 0; l < 2; l++) {
            int idx = tid + l * 256;          // 0..511
            int r = idx >> 3;
            int k4 = (idx & 7) << 2;
            int gr = row0 + r;
            float4 v = make_float4(0.f, 0.f, 0.f, 0.f);
            if (gr < NN)
                v = *reinterpret_cast<const float4*>(&src[gr * K + kc + k4]);
            if (BN) {
                int kk = kc + k4;
                v.x = fmaxf(fmaf(v.x, sc[kk + 0], sh[kk + 0]), 0.f);
                v.y = fmaxf(fmaf(v.y, sc[kk + 1], sh[kk + 1]), 0.f);
                v.z = fmaxf(fmaf(v.z, sc[kk + 2], sh[kk + 2]), 0.f);
                v.w = fmaxf(fmaf(v.w, sc[kk + 3], sh[kk + 3]), 0.f);
            }
            float4 h, lo;
            tf32split(v.x, h.x, lo.x); tf32split(v.y, h.y, lo.y);
            tf32split(v.z, h.z, lo.z); tf32split(v.w, h.w, lo.w);
            *reinterpret_cast<float4*>(&Ah[r][k4]) = h;
            *reinterpret_cast<float4*>(&Al[r][k4]) = lo;
        }
        // stage W chunk (32 k x 64 cols), hi/lo split
#pragma unroll
        for (int l = 0; l < 2; l++) {
            int idx = tid + l * 256;          // 0..511
            int k = idx >> 4;
            int c4 = (idx & 15) << 2;
            float4 v = *reinterpret_cast<const float4*>(&W[(kc + k) * 64 + c4]);
            float4 h, lo;
            tf32split(v.x, h.x, lo.x); tf32split(v.y, h.y, lo.y);
            tf32split(v.z, h.z, lo.z); tf32split(v.w, h.w, lo.w);
            *reinterpret_cast<float4*>(&Wh[k][c4]) = h;
            *reinterpret_cast<float4*>(&Wl[k][c4]) = lo;
        }
        __syncthreads();

#pragma unroll
        for (int kk = 0; kk < 32; kk += 8) {
            uint32_t ah0 = __float_as_uint(Ah[mr + gID][kk + tig]);
            uint32_t ah1 = __float_as_uint(Ah[mr + gID + 8][kk + tig]);
            uint32_t ah2 = __float_as_uint(Ah[mr + gID][kk + tig + 4]);
            uint32_t ah3 = __float_as_uint(Ah[mr + gID + 8][kk + tig + 4]);
            uint32_t al0 = __float_as_uint(Al[mr + gID][kk + tig]);
            uint32_t al1 = __float_as_uint(Al[mr + gID + 8][kk + tig]);
            uint32_t al2 = __float_as_uint(Al[mr + gID][kk + tig + 4]);
            uint32_t al3 = __float_as_uint(Al[mr + gID + 8][kk + tig + 4]);
#pragma unroll
            for (int j = 0; j < 4; j++) {
                uint32_t bh0 = __float_as_uint(Wh[kk + tig][nc + j * 8 + gID]);
                uint32_t bh1 = __float_as_uint(Wh[kk + tig + 4][nc + j * 8 + gID]);
                uint32_t bl0 = __float_as_uint(Wl[kk + tig][nc + j * 8 + gID]);
                uint32_t bl1 = __float_as_uint(Wl[kk + tig + 4][nc + j * 8 + gID]);
                mma_tf32(c[j], ah0, ah1, ah2, ah3, bl0, bl1);
                mma_tf32(c[j], al0, al1, al2, al3, bh0, bh1);
                mma_tf32(c[j], ah0, ah1, ah2, ah3, bh0, bh1);
            }
        }
        __syncthreads();
    }

    const float ep = 1.f + *epsp;
    const int r1 = row0 + mr + gID;
    const int r2 = r1 + 8;
#pragma unroll
    for (int j = 0; j < 4; j++) {
        int col = nc + j * 8 + tig * 2;
        if (r1 < NN) {
            *reinterpret_cast<float2*>(&g_y[r1 * 64 + col]) = make_float2(c[j].x, c[j].y);
            *reinterpret_cast<float2*>(&g_agg[r1 * 64 + col]) =
                make_float2(ep * c[j].x, ep * c[j].y);
        }
        if (r2 < NN) {
            *reinterpret_cast<float2*>(&g_y[r2 * 64 + col]) = make_float2(c[j].z, c[j].w);
            *reinterpret_cast<float2*>(&g_agg[r2 * 64 + col]) =
                make_float2(ep * c[j].z, ep * c[j].w);
        }
    }
}

// ---------------------------------------------------------------------------
// Scatter: g_agg[dst] += g_y[src], one 16B vector RED per thread (16 threads
// per edge). Block 0 also zeroes g_stats for the upcoming mlpB (safe: runs
// between the stats reader gemmA and the stats writer mlpB).
// ---------------------------------------------------------------------------
__global__ void __launch_bounds__(256) scatterK(const int* __restrict__ ei) {
    int idx = blockIdx.x * 256 + threadIdx.x;
    int e = idx >> 4;
    int q = idx & 15;
    int s = __ldg(&ei[e]);
    int d = __ldg(&ei[EE + e]);
    float4 v = reinterpret_cast<const float4*>(g_y)[s * 16 + q];
    float* dst = &g_agg[d * 64 + (q << 2)];
    asm volatile("red.global.add.v4.f32 [%0], {%1, %2, %3, %4};"
                 :: "l"(dst), "f"(v.x), "f"(v.y), "f"(v.z), "f"(v.w)
                 : "memory");
    if (blockIdx.x == 0 && threadIdx.x < 128) g_stats[threadIdx.x] = 0.f;
}

// ---------------------------------------------------------------------------
// Kernel B (3xTF32 tensor-core): h1 = relu(agg + ba); h2 = relu(h1 @ Wb + bb);
// write g_h; accumulate column sum/sumsq into g_stats.
// ---------------------------------------------------------------------------
__global__ void __launch_bounds__(256) mlpB(const float* __restrict__ W,
                                            const float* __restrict__ ba,
                                            const float* __restrict__ bb) {
    __shared__ float Ah[64][36], Al[64][36];
    __shared__ float Wh[32][72], Wl[32][72];
    __shared__ float ssum[64];
    __shared__ float ssq[64];

    const int tid = threadIdx.x;
    const int row0 = blockIdx.x * 64;

    if (tid < 64) { ssum[tid] = 0.f; ssq[tid] = 0.f; }

    const int w = tid >> 5;
    const int lane = tid & 31;
    const int gID = lane >> 2;
    const int tig = lane & 3;
    const int mr = (w & 3) * 16;
    const int nc = (w >> 2) * 32;

    float4 c[4] = {};

    for (int kc = 0; kc < 64; kc += 32) {
        // stage A chunk = relu(agg + ba), hi/lo split
#pragma unroll
        for (int l = 0; l < 2; l++) {
            int idx = tid + l * 256;
            int r = idx >> 3;
            int k4 = (idx & 7) << 2;
            int gr = row0 + r;
            float4 v = make_float4(0.f, 0.f, 0.f, 0.f);
            if (gr < NN) {
                v = *reinterpret_cast<const float4*>(&g_agg[gr * 64 + kc + k4]);
                float4 b = *reinterpret_cast<const float4*>(&ba[kc + k4]);
                v.x = fmaxf(v.x + b.x, 0.f);
                v.y = fmaxf(v.y + b.y, 0.f);
                v.z = fmaxf(v.z + b.z, 0.f);
                v.w = fmaxf(v.w + b.w, 0.f);
            }
            float4 h, lo;
            tf32split(v.x, h.x, lo.x); tf32split(v.y, h.y, lo.y);
            tf32split(v.z, h.z, lo.z); tf32split(v.w, h.w, lo.w);
            *reinterpret_cast<float4*>(&Ah[r][k4]) = h;
            *reinterpret_cast<float4*>(&Al[r][k4]) = lo;
        }
#pragma unroll
        for (int l = 0; l < 2; l++) {
            int idx = tid + l * 256;
            int k = idx >> 4;
            int c4 = (idx & 15) << 2;
            float4 v = *reinterpret_cast<const float4*>(&W[(kc + k) * 64 + c4]);
            float4 h, lo;
            tf32split(v.x, h.x, lo.x); tf32split(v.y, h.y, lo.y);
            tf32split(v.z, h.z, lo.z); tf32split(v.w, h.w, lo.w);
            *reinterpret_cast<float4*>(&Wh[k][c4]) = h;
            *reinterpret_cast<float4*>(&Wl[k][c4]) = lo;
        }
        __syncthreads();

#pragma unroll
        for (int kk = 0; kk < 32; kk += 8) {
            uint32_t ah0 = __float_as_uint(Ah[mr + gID][kk + tig]);
            uint32_t ah1 = __float_as_uint(Ah[mr + gID + 8][kk + tig]);
            uint32_t ah2 = __float_as_uint(Ah[mr + gID][kk + tig + 4]);
            uint32_t ah3 = __float_as_uint(Ah[mr + gID + 8][kk + tig + 4]);
            uint32_t al0 = __float_as_uint(Al[mr + gID][kk + tig]);
            uint32_t al1 = __float_as_uint(Al[mr + gID + 8][kk + tig]);
            uint32_t al2 = __float_as_uint(Al[mr + gID][kk + tig + 4]);
            uint32_t al3 = __float_as_uint(Al[mr + gID + 8][kk + tig + 4]);
#pragma unroll
            for (int j = 0; j < 4; j++) {
                uint32_t bh0 = __float_as_uint(Wh[kk + tig][nc + j * 8 + gID]);
                uint32_t bh1 = __float_as_uint(Wh[kk + tig + 4][nc + j * 8 + gID]);
                uint32_t bl0 = __float_as_uint(Wl[kk + tig][nc + j * 8 + gID]);
                uint32_t bl1 = __float_as_uint(Wl[kk + tig + 4][nc + j * 8 + gID]);
                mma_tf32(c[j], ah0, ah1, ah2, ah3, bl0, bl1);
                mma_tf32(c[j], al0, al1, al2, al3, bh0, bh1);
                mma_tf32(c[j], ah0, ah1, ah2, ah3, bh0, bh1);
            }
        }
        __syncthreads();
    }

    const int r1 = row0 + mr + gID;
    const int r2 = r1 + 8;
#pragma unroll
    for (int j = 0; j < 4; j++) {
        int col = nc + j * 8 + tig * 2;
        float b0 = __ldg(&bb[col]);
        float b1 = __ldg(&bb[col + 1]);
        float s0 = 0.f, s1 = 0.f, q0 = 0.f, q1 = 0.f;
        if (r1 < NN) {
            float h0 = fmaxf(c[j].x + b0, 0.f);
            float h1 = fmaxf(c[j].y + b1, 0.f);
            *reinterpret_cast<float2*>(&g_h[r1 * 64 + col]) = make_float2(h0, h1);
            s0 += h0; s1 += h1; q0 += h0 * h0; q1 += h1 * h1;
        }
        if (r2 < NN) {
            float h0 = fmaxf(c[j].z + b0, 0.f);
            float h1 = fmaxf(c[j].w + b1, 0.f);
            *reinterpret_cast<float2*>(&g_h[r2 * 64 + col]) = make_float2(h0, h1);
            s0 += h0; s1 += h1; q0 += h0 * h0; q1 += h1 * h1;
        }
        atomicAdd(&ssum[col], s0);
        atomicAdd(&ssum[col + 1], s1);
        atomicAdd(&ssq[col], q0);
        atomicAdd(&ssq[col + 1], q1);
    }
    __syncthreads();
    if (tid < 64) {
        atomicAdd(&g_stats[tid], ssum[tid]);
        atomicAdd(&g_stats[64 + tid], ssq[tid]);
    }
}

// ---------------------------------------------------------------------------
// Final head: out = relu(BN(g_h)) @ lin_w + lin_b  (64 -> 10), fp32.
// ---------------------------------------------------------------------------
__global__ void __launch_bounds__(256) finalLin(const float* __restrict__ lw,
                                                const float* __restrict__ lb,
                                                const float* __restrict__ gamma,
                                                const float* __restrict__ beta,
                                                float* __restrict__ out) {
    __shared__ float ws[64][10];
    __shared__ float sc[64], sh[64];
    __shared__ float lbs[10];
    int tid = threadIdx.x;
    for (int i = tid; i < 640; i += 256) ws[i / 10][i % 10] = lw[i];
    if (tid < 64) {
        const float inv = 1.f / (float)NN;
        float mean = g_stats[tid] * inv;
        float var = g_stats[64 + tid] * inv - mean * mean;
        float s = gamma[tid] * rsqrtf(var + 1e-5f);
        sc[tid] = s;
        sh[tid] = beta[tid] - mean * s;
    }
    if (tid < 10) lbs[tid] = lb[tid];
    __syncthreads();

    int r = blockIdx.x * 256 + tid;
    if (r >= NN) return;
    float acc[10];
#pragma unroll
    for (int c = 0; c < 10; c++) acc[c] = lbs[c];
#pragma unroll 16
    for (int k = 0; k < 64; k++) {
        float hv = fmaxf(fmaf(g_h[r * 64 + k], sc[k], sh[k]), 0.f);
#pragma unroll
        for (int c = 0; c < 10; c++) acc[c] = fmaf(hv, ws[k][c], acc[c]);
    }
#pragma unroll
    for (int c = 0; c < 10; c++) out[r * 10 + c] = acc[c];
}

// ---------------------------------------------------------------------------
extern "C" void kernel_launch(void* const* d_in, const int* in_sizes, int n_in,
                              void* d_out, int out_size) {
    const float* x    = (const float*)d_in[0];
    const int* ei     = (const int*)d_in[1];   // int64 inputs delivered as int32
    const float* eps1 = (const float*)d_in[2];
    const float* w1a  = (const float*)d_in[3];
    const float* b1a  = (const float*)d_in[4];
    const float* w1b  = (const float*)d_in[5];
    const float* b1b  = (const float*)d_in[6];
    const float* g1   = (const float*)d_in[7];
    const float* be1  = (const float*)d_in[8];
    const float* eps2 = (const float*)d_in[9];
    const float* w2a  = (const float*)d_in[10];
    const float* b2a  = (const float*)d_in[11];
    const float* w2b  = (const float*)d_in[12];
    const float* b2b  = (const float*)d_in[13];
    const float* g2   = (const float*)d_in[14];
    const float* be2  = (const float*)d_in[15];
    const float* eps3 = (const float*)d_in[16];
    const float* w3a  = (const float*)d_in[17];
    const float* b3a  = (const float*)d_in[18];
    const float* w3b  = (const float*)d_in[19];
    const float* b3b  = (const float*)d_in[20];
    const float* g3   = (const float*)d_in[21];
    const float* be3  = (const float*)d_in[22];
    const float* lw   = (const float*)d_in[23];
    const float* lb   = (const float*)d_in[24];
    float* out = (float*)d_out;

    const int gb = (NN + 63) / 64;            // 782 row-tiles
    const int sg = (EE * 16) / 256;           // 50000 scatter blocks

    // Layer 1 (K = 128, input = x, no BN on input)
    gemmA<128, false><<<gb, 256>>>(x, w1a, eps1, nullptr, nullptr);
    scatterK<<<sg, 256>>>(ei);
    mlpB<<<gb, 256>>>(w1b, b1a, b1b);

    // Layer 2 (input = relu(BN(g_h)) applied on the fly; stats from mlpB L1)
    gemmA<64, true><<<gb, 256>>>(nullptr, w2a, eps2, g1, be1);
    scatterK<<<sg, 256>>>(ei);
    mlpB<<<gb, 256>>>(w2b, b2a, b2b);

    // Layer 3
    gemmA<64, true><<<gb, 256>>>(nullptr, w3a, eps3, g2, be2);
    scatterK<<<sg, 256>>>(ei);
    mlpB<<<gb, 256>>>(w3b, b3a, b3b);

    // Head (BN of layer 3 applied on the fly)
    finalLin<<<(NN + 255) / 256, 256>>>(lw, lb, g3, be3, out);
}

// round 14
// speedup vs baseline: 1.1322x; 1.1322x over previous
#include <cuda_runtime.h>
#include <cuda_bf16.h>
#include <cstdint>

// Problem constants
#define NN 50000
#define EE 800000

// ---------------- device scratch (no allocations allowed) ----------------
__device__ __align__(16) float g_y[NN * 64];     // pre-aggregation GEMM output
__device__ __align__(16) float g_agg[NN * 64];   // aggregation accumulator
__device__ __align__(16) float g_h[NN * 64];     // post-MLP (pre-BN) features
__device__ float g_stats[128];                   // [0:64) sum, [64:128) sumsq

// ---------------- bf16 hi/lo split helpers ----------------
// Split (x0,x1) into bf16 hi-pair and bf16 lo-pair (packed, x0 in low bits).
__device__ __forceinline__ uint32_t bsplit2(float x0, float x1, uint32_t& lo_pair) {
    __nv_bfloat16 h0 = __float2bfloat16_rn(x0);
    __nv_bfloat16 h1 = __float2bfloat16_rn(x1);
    float r0 = x0 - __bfloat162float(h0);
    float r1 = x1 - __bfloat162float(h1);
    __nv_bfloat16 l0 = __float2bfloat16_rn(r0);
    __nv_bfloat16 l1 = __float2bfloat16_rn(r1);
    lo_pair = ((uint32_t)__bfloat16_as_ushort(l1) << 16) | __bfloat16_as_ushort(l0);
    return ((uint32_t)__bfloat16_as_ushort(h1) << 16) | __bfloat16_as_ushort(h0);
}

__device__ __forceinline__ void mma_bf16(float4& c, uint32_t a0, uint32_t a1,
                                         uint32_t a2, uint32_t a3,
                                         uint32_t b0, uint32_t b1) {
    asm volatile(
        "mma.sync.aligned.m16n8k16.row.col.f32.bf16.bf16.f32 "
        "{%0,%1,%2,%3}, {%4,%5,%6,%7}, {%8,%9}, {%0,%1,%2,%3};"
        : "+f"(c.x), "+f"(c.y), "+f"(c.z), "+f"(c.w)
        : "r"(a0), "r"(a1), "r"(a2), "r"(a3), "r"(b0), "r"(b1));
}

// Warp-tile mainloop over one staged 64-k chunk (3-term bf16 compensation).
// Ah/Al: [64][36] uint32 (row, k-pair). Wh/Wl: [64][36] (n-row, k-pair).
__device__ __forceinline__ void mma_chunk(const uint32_t (*Ah)[36],
                                          const uint32_t (*Al)[36],
                                          const uint32_t (*Wh)[36],
                                          const uint32_t (*Wl)[36],
                                          int mr, int nc, int gID, int tig,
                                          float4 c[4]) {
#pragma unroll
    for (int kk = 0; kk < 4; kk++) {           // 4 k16 steps
        const int kb = kk * 8;
        uint32_t ah0 = Ah[mr + gID][kb + tig];
        uint32_t ah1 = Ah[mr + gID + 8][kb + tig];
        uint32_t ah2 = Ah[mr + gID][kb + tig + 4];
        uint32_t ah3 = Ah[mr + gID + 8][kb + tig + 4];
        uint32_t al0 = Al[mr + gID][kb + tig];
        uint32_t al1 = Al[mr + gID + 8][kb + tig];
        uint32_t al2 = Al[mr + gID][kb + tig + 4];
        uint32_t al3 = Al[mr + gID + 8][kb + tig + 4];
#pragma unroll
        for (int j = 0; j < 4; j++) {
            int col = nc + j * 8 + gID;
            uint32_t bh0 = Wh[col][kb + tig];
            uint32_t bh1 = Wh[col][kb + tig + 4];
            uint32_t bl0 = Wl[col][kb + tig];
            uint32_t bl1 = Wl[col][kb + tig + 4];
            mma_bf16(c[j], ah0, ah1, ah2, ah3, bl0, bl1);
            mma_bf16(c[j], al0, al1, al2, al3, bh0, bh1);
            mma_bf16(c[j], ah0, ah1, ah2, ah3, bh0, bh1);
        }
    }
}

// ---------------------------------------------------------------------------
// Kernel A (bf16 3-term tensor-core): y = act(src) @ W  (N x K @ K x 64).
// act = identity (layer 1) or BN+ReLU (layers 2,3). Writes g_y and
// g_agg = (1+eps)*y. 64x64 block tile; 8 warps, 16x32 warp tiles.
// ---------------------------------------------------------------------------
template <int K, bool BN>
__global__ void __launch_bounds__(256) gemmA(const float* __restrict__ A,
                                             const float* __restrict__ W,
                                             const float* __restrict__ epsp,
                                             const float* __restrict__ gamma,
                                             const float* __restrict__ beta) {
    __shared__ uint32_t Ah[64][36], Al[64][36];   // A hi/lo (row, k-pair)
    __shared__ uint32_t Wh[64][36], Wl[64][36];   // W^T hi/lo (n-row, k-pair)
    __shared__ float sc[64], sh[64];

    const int tid = threadIdx.x;
    const int row0 = blockIdx.x * 64;

    const float* __restrict__ src = BN ? (const float*)g_h : A;

    if (BN) {
        if (tid < 64) {
            const float inv = 1.f / (float)NN;
            float mean = g_stats[tid] * inv;
            float var = g_stats[64 + tid] * inv - mean * mean;
            float s = gamma[tid] * rsqrtf(var + 1e-5f);
            sc[tid] = s;
            sh[tid] = beta[tid] - mean * s;
        }
        __syncthreads();
    }

    const int w = tid >> 5;
    const int lane = tid & 31;
    const int gID = lane >> 2;
    const int tig = lane & 3;
    const int mr = (w & 3) * 16;        // warp m-offset in tile
    const int nc = (w >> 2) * 32;       // warp n-offset in tile

    float4 c[4] = {};

    for (int kc = 0; kc < K; kc += 64) {
        // stage A chunk (64 rows x 64 k): BN+ReLU, split, pack pairs
#pragma unroll
        for (int l = 0; l < 4; l++) {
            int idx = tid + l * 256;
            int r = idx >> 4;
            int k4 = (idx & 15) << 2;
            int gr = row0 + r;
            float4 v = make_float4(0.f, 0.f, 0.f, 0.f);
            if (gr < NN)
                v = *reinterpret_cast<const float4*>(&src[gr * K + kc + k4]);
            if (BN) {
                v.x = fmaxf(fmaf(v.x, sc[k4 + 0], sh[k4 + 0]), 0.f);
                v.y = fmaxf(fmaf(v.y, sc[k4 + 1], sh[k4 + 1]), 0.f);
                v.z = fmaxf(fmaf(v.z, sc[k4 + 2], sh[k4 + 2]), 0.f);
                v.w = fmaxf(fmaf(v.w, sc[k4 + 3], sh[k4 + 3]), 0.f);
            }
            uint32_t lo0, lo1;
            uint32_t hi0 = bsplit2(v.x, v.y, lo0);
            uint32_t hi1 = bsplit2(v.z, v.w, lo1);
            int k2 = k4 >> 1;
            Ah[r][k2] = hi0; Ah[r][k2 + 1] = hi1;
            Al[r][k2] = lo0; Al[r][k2 + 1] = lo1;
        }
        // stage W chunk transposed: Wt[n][k2] from W[(kc+2*k2)*64 + n]
#pragma unroll
        for (int l = 0; l < 8; l++) {
            int idx = tid + l * 256;     // 0..2047 = 64 n x 32 k2
            int n = idx & 63;
            int k2 = idx >> 6;
            float w0 = W[(kc + 2 * k2) * 64 + n];
            float w1 = W[(kc + 2 * k2 + 1) * 64 + n];
            uint32_t lo;
            uint32_t hi = bsplit2(w0, w1, lo);
            Wh[n][k2] = hi;
            Wl[n][k2] = lo;
        }
        __syncthreads();

        mma_chunk(Ah, Al, Wh, Wl, mr, nc, gID, tig, c);
        __syncthreads();
    }

    const float ep = 1.f + *epsp;
    const int r1 = row0 + mr + gID;
    const int r2 = r1 + 8;
#pragma unroll
    for (int j = 0; j < 4; j++) {
        int col = nc + j * 8 + tig * 2;
        if (r1 < NN) {
            *reinterpret_cast<float2*>(&g_y[r1 * 64 + col]) = make_float2(c[j].x, c[j].y);
            *reinterpret_cast<float2*>(&g_agg[r1 * 64 + col]) =
                make_float2(ep * c[j].x, ep * c[j].y);
        }
        if (r2 < NN) {
            *reinterpret_cast<float2*>(&g_y[r2 * 64 + col]) = make_float2(c[j].z, c[j].w);
            *reinterpret_cast<float2*>(&g_agg[r2 * 64 + col]) =
                make_float2(ep * c[j].z, ep * c[j].w);
        }
    }
}

// ---------------------------------------------------------------------------
// Scatter: g_agg[dst] += g_y[src], one 16B vector RED per thread (16 threads
// per edge). Block 0 also zeroes g_stats for the upcoming mlpB.
// ---------------------------------------------------------------------------
__global__ void __launch_bounds__(256) scatterK(const int* __restrict__ ei) {
    int idx = blockIdx.x * 256 + threadIdx.x;
    int e = idx >> 4;
    int q = idx & 15;
    int s = __ldg(&ei[e]);
    int d = __ldg(&ei[EE + e]);
    float4 v = reinterpret_cast<const float4*>(g_y)[s * 16 + q];
    float* dst = &g_agg[d * 64 + (q << 2)];
    asm volatile("red.global.add.v4.f32 [%0], {%1, %2, %3, %4};"
                 :: "l"(dst), "f"(v.x), "f"(v.y), "f"(v.z), "f"(v.w)
                 : "memory");
    if (blockIdx.x == 0 && threadIdx.x < 128) g_stats[threadIdx.x] = 0.f;
}

// ---------------------------------------------------------------------------
// Kernel B (bf16 3-term tensor-core): h1 = relu(agg + ba);
// h2 = relu(h1 @ Wb + bb); write g_h; accumulate col sum/sumsq into g_stats.
// ---------------------------------------------------------------------------
__global__ void __launch_bounds__(256) mlpB(const float* __restrict__ W,
                                            const float* __restrict__ ba,
                                            const float* __restrict__ bb) {
    __shared__ uint32_t Ah[64][36], Al[64][36];
    __shared__ uint32_t Wh[64][36], Wl[64][36];
    __shared__ float ssum[64];
    __shared__ float ssq[64];

    const int tid = threadIdx.x;
    const int row0 = blockIdx.x * 64;

    if (tid < 64) { ssum[tid] = 0.f; ssq[tid] = 0.f; }

    // stage A = relu(agg + ba), split
#pragma unroll
    for (int l = 0; l < 4; l++) {
        int idx = tid + l * 256;
        int r = idx >> 4;
        int k4 = (idx & 15) << 2;
        int gr = row0 + r;
        float4 v = make_float4(0.f, 0.f, 0.f, 0.f);
        if (gr < NN) {
            v = *reinterpret_cast<const float4*>(&g_agg[gr * 64 + k4]);
            float4 b = *reinterpret_cast<const float4*>(&ba[k4]);
            v.x = fmaxf(v.x + b.x, 0.f);
            v.y = fmaxf(v.y + b.y, 0.f);
            v.z = fmaxf(v.z + b.z, 0.f);
            v.w = fmaxf(v.w + b.w, 0.f);
        }
        uint32_t lo0, lo1;
        uint32_t hi0 = bsplit2(v.x, v.y, lo0);
        uint32_t hi1 = bsplit2(v.z, v.w, lo1);
        int k2 = k4 >> 1;
        Ah[r][k2] = hi0; Ah[r][k2 + 1] = hi1;
        Al[r][k2] = lo0; Al[r][k2 + 1] = lo1;
    }
    // stage W transposed, split
#pragma unroll
    for (int l = 0; l < 8; l++) {
        int idx = tid + l * 256;
        int n = idx & 63;
        int k2 = idx >> 6;
        float w0 = W[(2 * k2) * 64 + n];
        float w1 = W[(2 * k2 + 1) * 64 + n];
        uint32_t lo;
        uint32_t hi = bsplit2(w0, w1, lo);
        Wh[n][k2] = hi;
        Wl[n][k2] = lo;
    }
    __syncthreads();

    const int w = tid >> 5;
    const int lane = tid & 31;
    const int gID = lane >> 2;
    const int tig = lane & 3;
    const int mr = (w & 3) * 16;
    const int nc = (w >> 2) * 32;

    float4 c[4] = {};
    mma_chunk(Ah, Al, Wh, Wl, mr, nc, gID, tig, c);

    const int r1 = row0 + mr + gID;
    const int r2 = r1 + 8;
#pragma unroll
    for (int j = 0; j < 4; j++) {
        int col = nc + j * 8 + tig * 2;
        float b0 = __ldg(&bb[col]);
        float b1 = __ldg(&bb[col + 1]);
        float s0 = 0.f, s1 = 0.f, q0 = 0.f, q1 = 0.f;
        if (r1 < NN) {
            float h0 = fmaxf(c[j].x + b0, 0.f);
            float h1 = fmaxf(c[j].y + b1, 0.f);
            *reinterpret_cast<float2*>(&g_h[r1 * 64 + col]) = make_float2(h0, h1);
            s0 += h0; s1 += h1; q0 += h0 * h0; q1 += h1 * h1;
        }
        if (r2 < NN) {
            float h0 = fmaxf(c[j].z + b0, 0.f);
            float h1 = fmaxf(c[j].w + b1, 0.f);
            *reinterpret_cast<float2*>(&g_h[r2 * 64 + col]) = make_float2(h0, h1);
            s0 += h0; s1 += h1; q0 += h0 * h0; q1 += h1 * h1;
        }
        atomicAdd(&ssum[col], s0);
        atomicAdd(&ssum[col + 1], s1);
        atomicAdd(&ssq[col], q0);
        atomicAdd(&ssq[col + 1], q1);
    }
    __syncthreads();
    if (tid < 64) {
        atomicAdd(&g_stats[tid], ssum[tid]);
        atomicAdd(&g_stats[64 + tid], ssq[tid]);
    }
}

// ---------------------------------------------------------------------------
// Final head: out = relu(BN(g_h)) @ lin_w + lin_b  (64 -> 10), fp32.
// ---------------------------------------------------------------------------
__global__ void __launch_bounds__(256) finalLin(const float* __restrict__ lw,
                                                const float* __restrict__ lb,
                                                const float* __restrict__ gamma,
                                                const float* __restrict__ beta,
                                                float* __restrict__ out) {
    __shared__ float ws[64][10];
    __shared__ float sc[64], sh[64];
    __shared__ float lbs[10];
    int tid = threadIdx.x;
    for (int i = tid; i < 640; i += 256) ws[i / 10][i % 10] = lw[i];
    if (tid < 64) {
        const float inv = 1.f / (float)NN;
        float mean = g_stats[tid] * inv;
        float var = g_stats[64 + tid] * inv - mean * mean;
        float s = gamma[tid] * rsqrtf(var + 1e-5f);
        sc[tid] = s;
        sh[tid] = beta[tid] - mean * s;
    }
    if (tid < 10) lbs[tid] = lb[tid];
    __syncthreads();

    int r = blockIdx.x * 256 + tid;
    if (r >= NN) return;
    float acc[10];
#pragma unroll
    for (int c = 0; c < 10; c++) acc[c] = lbs[c];
#pragma unroll 16
    for (int k = 0; k < 64; k++) {
        float hv = fmaxf(fmaf(g_h[r * 64 + k], sc[k], sh[k]), 0.f);
#pragma unroll
        for (int c = 0; c < 10; c++) acc[c] = fmaf(hv, ws[k][c], acc[c]);
    }
#pragma unroll
    for (int c = 0; c < 10; c++) out[r * 10 + c] = acc[c];
}

// ---------------------------------------------------------------------------
extern "C" void kernel_launch(void* const* d_in, const int* in_sizes, int n_in,
                              void* d_out, int out_size) {
    const float* x    = (const float*)d_in[0];
    const int* ei     = (const int*)d_in[1];   // int64 inputs delivered as int32
    const float* eps1 = (const float*)d_in[2];
    const float* w1a  = (const float*)d_in[3];
    const float* b1a  = (const float*)d_in[4];
    const float* w1b  = (const float*)d_in[5];
    const float* b1b  = (const float*)d_in[6];
    const float* g1   = (const float*)d_in[7];
    const float* be1  = (const float*)d_in[8];
    const float* eps2 = (const float*)d_in[9];
    const float* w2a  = (const float*)d_in[10];
    const float* b2a  = (const float*)d_in[11];
    const float* w2b  = (const float*)d_in[12];
    const float* b2b  = (const float*)d_in[13];
    const float* g2   = (const float*)d_in[14];
    const float* be2  = (const float*)d_in[15];
    const float* eps3 = (const float*)d_in[16];
    const float* w3a  = (const float*)d_in[17];
    const float* b3a  = (const float*)d_in[18];
    const float* w3b  = (const float*)d_in[19];
    const float* b3b  = (const float*)d_in[20];
    const float* g3   = (const float*)d_in[21];
    const float* be3  = (const float*)d_in[22];
    const float* lw   = (const float*)d_in[23];
    const float* lb   = (const float*)d_in[24];
    float* out = (float*)d_out;

    const int gb = (NN + 63) / 64;            // 782 row-tiles
    const int sg = (EE * 16) / 256;           // 50000 scatter blocks

    // Layer 1 (K = 128, input = x, no BN on input)
    gemmA<128, false><<<gb, 256>>>(x, w1a, eps1, nullptr, nullptr);
    scatterK<<<sg, 256>>>(ei);
    mlpB<<<gb, 256>>>(w1b, b1a, b1b);

    // Layer 2 (input = relu(BN(g_h)) applied on the fly; stats from mlpB L1)
    gemmA<64, true><<<gb, 256>>>(nullptr, w2a, eps2, g1, be1);
    scatterK<<<sg, 256>>>(ei);
    mlpB<<<gb, 256>>>(w2b, b2a, b2b);

    // Layer 3
    gemmA<64, true><<<gb, 256>>>(nullptr, w3a, eps3, g2, be2);
    scatterK<<<sg, 256>>>(ei);
    mlpB<<<gb, 256>>>(w3b, b3a, b3b);

    // Head (BN of layer 3 applied on the fly)
    finalLin<<<(NN + 255) / 256, 256>>>(lw, lb, g3, be3, out);
}